// round 1
// baseline (speedup 1.0000x reference)
#include <cuda_runtime.h>
#include <cuda_bf16.h>

// ---------------------------------------------------------------------------
// Problem: Galerkin linear attention.
//   b=4, n=8192, dim=256, heads=8, dh=64, inner=512
//   qkv = x @ w_qkv ; k,v instance-normalized per token over dh
//   dots[b,h] = sum_n khat^T vhat ; out = (q @ dots)/n ; final = out @ w_out + b_out
// Restructured: final[b] = x[b] @ Wfinal[b] + b_out, where
//   Wfinal[b] = w_q @ blockdiag(dots[b,h]) @ w_out / n   (q never materialized)
// ---------------------------------------------------------------------------

#define BATCH   4
#define NTOK    8192
#define DIM     256
#define HEADS   8
#define DH      64
#define INNER   512          // HEADS*DH
#define NCHUNK  8            // token chunks per (b,h) for partial dots
#define CHUNKTOK (NTOK / NCHUNK)   // 1024

// scratch (device globals: allocation-free per harness rules)
__device__ float g_kv[(long long)BATCH * NTOK * (2 * INNER)];  // [b,n,1024] k|v, 134 MB
__device__ float g_part[32 * NCHUNK * DH * DH];                // partial dots
__device__ float g_dots[32 * DH * DH];                         // [b*h, 64, 64]
__device__ float g_A2[BATCH * INNER * DIM];                    // blockdiag(dots)@w_out
__device__ float g_Wf[BATCH * DIM * DIM];                      // Wfinal

// ---------------------------------------------------------------------------
// Generic tiled SGEMM: C[bz] = alpha * A[bz] @ B[bz] (+ bias per column)
// BM=BN=128, BK=8, 8x8 per thread, 256 threads. Requires M%128==0, N%128==0,
// K%8==0, 16B-aligned rows (all true for our shapes).
// ---------------------------------------------------------------------------
#define BM 128
#define BN 128
#define BK 8
#define TM 8
#define TN 8

__global__ __launch_bounds__(256) void sgemm_k(
    const float* __restrict__ A, int lda, long long sA,
    const float* __restrict__ B, int ldb, long long sB,
    float* __restrict__ C, int ldc, long long sC,
    int K, const float* __restrict__ bias, float alpha)
{
    __shared__ float As[BK * BM];
    __shared__ float Bs[BK * BN];

    const int tid = threadIdx.x;
    const int bx = blockIdx.x, by = blockIdx.y, bz = blockIdx.z;

    A += (long long)bz * sA + (long long)by * BM * lda;
    B += (long long)bz * sB + (long long)bx * BN;
    C += (long long)bz * sC + (long long)by * BM * ldc + (long long)bx * BN;

    const int aRow = tid >> 1;            // 0..127
    const int aCol = (tid & 1) << 2;      // 0 or 4
    const int bRow = tid >> 5;            // 0..7
    const int bCol = (tid & 31) << 2;     // 0..124

    const int tRow = (tid >> 4) * TM;     // 0..120
    const int tCol = (tid & 15) * TN;     // 0..120

    float acc[TM][TN] = {};
    float rM[TM], rN[TN];

    for (int k0 = 0; k0 < K; k0 += BK) {
        float4 a4 = *reinterpret_cast<const float4*>(&A[(long long)aRow * lda + k0 + aCol]);
        As[(aCol + 0) * BM + aRow] = a4.x;
        As[(aCol + 1) * BM + aRow] = a4.y;
        As[(aCol + 2) * BM + aRow] = a4.z;
        As[(aCol + 3) * BM + aRow] = a4.w;
        float4 b4 = *reinterpret_cast<const float4*>(&B[(long long)(k0 + bRow) * ldb + bCol]);
        *reinterpret_cast<float4*>(&Bs[bRow * BN + bCol]) = b4;
        __syncthreads();

        #pragma unroll
        for (int kk = 0; kk < BK; ++kk) {
            #pragma unroll
            for (int i = 0; i < TM; ++i) rM[i] = As[kk * BM + tRow + i];
            #pragma unroll
            for (int j = 0; j < TN; ++j) rN[j] = Bs[kk * BN + tCol + j];
            #pragma unroll
            for (int i = 0; i < TM; ++i)
                #pragma unroll
                for (int j = 0; j < TN; ++j)
                    acc[i][j] += rM[i] * rN[j];
        }
        __syncthreads();
    }

    #pragma unroll
    for (int i = 0; i < TM; ++i) {
        #pragma unroll
        for (int j = 0; j < TN; j += 4) {
            float4 o;
            o.x = alpha * acc[i][j + 0];
            o.y = alpha * acc[i][j + 1];
            o.z = alpha * acc[i][j + 2];
            o.w = alpha * acc[i][j + 3];
            if (bias) {
                const int col = bx * BN + tCol + j;
                o.x += bias[col + 0];
                o.y += bias[col + 1];
                o.z += bias[col + 2];
                o.w += bias[col + 3];
            }
            *reinterpret_cast<float4*>(&C[(long long)(tRow + i) * ldc + tCol + j]) = o;
        }
    }
}

// ---------------------------------------------------------------------------
// Fused instance-norm(k), instance-norm(v) + partial dots = sum_t khat^T vhat.
// grid: (chunk=NCHUNK, bh=32). Each block: 1024 tokens in 16 tiles of 64.
// Deterministic two-stage reduction (no float atomics).
// ---------------------------------------------------------------------------
__global__ __launch_bounds__(256) void norm_dots_partial(
    const float* __restrict__ kv, float* __restrict__ part)
{
    const int chunk = blockIdx.x;          // 0..NCHUNK-1
    const int bh    = blockIdx.y;          // 0..31
    const int b = bh >> 3, h = bh & 7;

    __shared__ float sk[64][65];
    __shared__ float sv[64][65];

    const int tid = threadIdx.x;
    const int e0 = (tid >> 4) << 2;        // dots row base (k dim)
    const int f0 = (tid & 15) << 2;        // dots col base (v dim)

    const float* base_k = kv + (long long)b * NTOK * (2 * INNER) + h * DH;
    const float* base_v = base_k + INNER;

    float acc[4][4] = {};

    for (int step = 0; step < CHUNKTOK / 64; ++step) {
        const int tok0 = chunk * CHUNKTOK + step * 64;
        // load 64 tokens x 64 dims for k and v
        for (int i = tid; i < 64 * 64; i += 256) {
            const int r = i >> 6, d = i & 63;
            const long long off = (long long)(tok0 + r) * (2 * INNER) + d;
            sk[r][d] = base_k[off];
            sv[r][d] = base_v[off];
        }
        __syncthreads();
        // instance norm per token row (biased var, eps=1e-5)
        if (tid < 128) {
            const int r = tid & 63;
            float* row = (tid < 64) ? sk[r] : sv[r];
            float s = 0.f, s2 = 0.f;
            #pragma unroll 8
            for (int d = 0; d < 64; ++d) { float x = row[d]; s += x; s2 += x * x; }
            const float mu  = s * (1.0f / 64.0f);
            const float var = s2 * (1.0f / 64.0f) - mu * mu;
            const float inv = rsqrtf(var + 1e-5f);
            #pragma unroll 8
            for (int d = 0; d < 64; ++d) row[d] = (row[d] - mu) * inv;
        }
        __syncthreads();
        // accumulate 64x64 outer products over 64 tokens
        #pragma unroll 4
        for (int t = 0; t < 64; ++t) {
            float ke[4], vf[4];
            #pragma unroll
            for (int i = 0; i < 4; ++i) ke[i] = sk[t][e0 + i];
            #pragma unroll
            for (int j = 0; j < 4; ++j) vf[j] = sv[t][f0 + j];
            #pragma unroll
            for (int i = 0; i < 4; ++i)
                #pragma unroll
                for (int j = 0; j < 4; ++j)
                    acc[i][j] += ke[i] * vf[j];
        }
        __syncthreads();
    }

    float* out = part + (long long)(bh * NCHUNK + chunk) * (DH * DH);
    #pragma unroll
    for (int i = 0; i < 4; ++i)
        #pragma unroll
        for (int j = 0; j < 4; ++j)
            out[(e0 + i) * DH + f0 + j] = acc[i][j];
}

__global__ __launch_bounds__(256) void reduce_dots(
    const float* __restrict__ part, float* __restrict__ dots)
{
    const int bh = blockIdx.x;
    for (int i = threadIdx.x; i < DH * DH; i += 256) {
        float s = 0.f;
        #pragma unroll
        for (int c = 0; c < NCHUNK; ++c)
            s += part[(long long)(bh * NCHUNK + c) * (DH * DH) + i];
        dots[bh * DH * DH + i] = s;
    }
}

// A2[b, h*64+e, j] = sum_f dots[b,h][e,f] * w_out[h*64+f, j]
__global__ __launch_bounds__(256) void dots_wout(
    const float* __restrict__ dots, const float* __restrict__ w_out,
    float* __restrict__ A2)
{
    const int bh = blockIdx.x;
    const int b = bh >> 3, h = bh & 7;
    __shared__ float sd[DH * DH];
    for (int i = threadIdx.x; i < DH * DH; i += 256) sd[i] = dots[bh * DH * DH + i];
    __syncthreads();
    for (int idx = threadIdx.x; idx < DH * DIM; idx += 256) {
        const int e = idx >> 8;          // 0..63
        const int j = idx & 255;         // 0..255
        float s = 0.f;
        #pragma unroll 8
        for (int f = 0; f < DH; ++f)
            s += sd[e * DH + f] * w_out[(h * DH + f) * DIM + j];
        A2[((long long)b * INNER + h * DH + e) * DIM + j] = s;
    }
}

// ---------------------------------------------------------------------------
extern "C" void kernel_launch(void* const* d_in, const int* in_sizes, int n_in,
                              void* d_out, int out_size)
{
    const float* x      = (const float*)d_in[0];  // [4, 8192, 256]
    const float* w_qkv  = (const float*)d_in[1];  // [256, 1536]
    const float* w_out  = (const float*)d_in[2];  // [512, 256]
    const float* b_out  = (const float*)d_in[3];  // [256]
    float*       out    = (float*)d_out;          // [4, 8192, 256]

    float *kv, *part, *dots, *A2, *Wf;
    cudaGetSymbolAddress((void**)&kv,   g_kv);
    cudaGetSymbolAddress((void**)&part, g_part);
    cudaGetSymbolAddress((void**)&dots, g_dots);
    cudaGetSymbolAddress((void**)&A2,   g_A2);
    cudaGetSymbolAddress((void**)&Wf,   g_Wf);

    // 1) kv = x @ w_qkv[:, 512:1536]   (M=32768, K=256, N=1024)
    sgemm_k<<<dim3((2 * INNER) / BN, (BATCH * NTOK) / BM, 1), 256>>>(
        x, DIM, 0,
        w_qkv + INNER, 3 * INNER, 0,
        kv, 2 * INNER, 0,
        DIM, nullptr, 1.0f);

    // 2) instance norm + partial dots, then deterministic reduce
    norm_dots_partial<<<dim3(NCHUNK, 32), 256>>>(kv, part);
    reduce_dots<<<32, 256>>>(part, dots);

    // 3) A2 = blockdiag(dots) @ w_out ;  Wf[b] = w_q @ A2[b] / n
    dots_wout<<<32, 256>>>(dots, w_out, A2);
    sgemm_k<<<dim3(DIM / BN, DIM / BM, BATCH), 256>>>(
        w_qkv, 3 * INNER, 0,
        A2, DIM, (long long)INNER * DIM,
        Wf, DIM, (long long)DIM * DIM,
        INNER, nullptr, 1.0f / (float)NTOK);

    // 4) out[b] = x[b] @ Wf[b] + b_out   (M=8192, K=256, N=256 per batch)
    sgemm_k<<<dim3(DIM / BN, NTOK / BM, BATCH), 256>>>(
        x, DIM, (long long)NTOK * DIM,
        Wf, DIM, (long long)DIM * DIM,
        out, DIM, (long long)NTOK * DIM,
        DIM, b_out, 1.0f);
}

// round 2
// speedup vs baseline: 2.9489x; 2.9489x over previous
#include <cuda_runtime.h>
#include <cuda_bf16.h>
#include <cstdint>

// ---------------------------------------------------------------------------
// Galerkin linear attention, restructured:
//   kv = x @ w_qkv[:,512:]            (tf32 tensor-core GEMM)
//   k,v instance-norm + dots = sum khat^T vhat   (fused, fp32)
//   A2 = blockdiag(dots) @ w_out      (fp32, parallelized)
//   Wf[b] = w_q @ A2[b] / n           (fp32 SIMT, tiny)
//   out[b] = x[b] @ Wf[b] + b_out     (tf32 tensor-core GEMM)
// ---------------------------------------------------------------------------

#define BATCH   4
#define NTOK    8192
#define DIM     256
#define HEADS   8
#define DH      64
#define INNER   512
#define NCHUNK  16
#define CHUNKTOK (NTOK / NCHUNK)   // 512

__device__ float g_kv[(long long)BATCH * NTOK * (2 * INNER)];   // 134 MB
__device__ float g_part[32 * NCHUNK * DH * DH];
__device__ float g_dots[32 * DH * DH];
__device__ float g_A2[BATCH * INNER * DIM];
__device__ float g_Wf[BATCH * DIM * DIM];

// ===========================================================================
// TF32 tensor-core GEMM: C[bz] = alpha * A[bz] @ B[bz] (+bias)
// A row-major [M,K], B row-major [K,N]. BM=BN=128, BK=16, 256 thr (8 warps),
// warp tile 64x32 via m16n8k8. Requires M%128==0, N%128==0, K%16==0.
// ===========================================================================
#define BM 128
#define BN 128
#define BKT 16

__device__ __forceinline__ uint32_t f2tf32(float f) {
    uint32_t r;
    asm("cvt.rna.tf32.f32 %0, %1;" : "=r"(r) : "f"(f));
    return r;
}

__global__ __launch_bounds__(256) void gemm_tf32(
    const float* __restrict__ A, int lda, long long sA,
    const float* __restrict__ B, int ldb, long long sB,
    float* __restrict__ C, int ldc, long long sC,
    int K, const float* __restrict__ bias, float alpha)
{
    __shared__ uint32_t As[2][BKT][BM + 4];   // [k][m]
    __shared__ uint32_t Bs[2][BKT][BN + 4];   // [k][n]

    const int tid = threadIdx.x;
    const int bx = blockIdx.x, by = blockIdx.y, bz = blockIdx.z;

    A += (long long)bz * sA + (long long)by * BM * lda;
    B += (long long)bz * sB + (long long)bx * BN;
    C += (long long)bz * sC + (long long)by * BM * ldc + (long long)bx * BN;

    // staging indices
    const int aRow = tid >> 2;            // 0..63 (plus +64)
    const int aCol = (tid & 3) << 2;      // 0,4,8,12
    const int bRow = tid >> 5;            // 0..7 (plus +8)
    const int bCol = (tid & 31) << 2;     // 0..124

    const int lane = tid & 31, wid = tid >> 5;
    const int warpM = (wid >> 2) * 64;    // 0 or 64
    const int warpN = (wid & 3) * 32;     // 0,32,64,96
    const int g = lane >> 2, tg = lane & 3;

    float acc[4][4][4];
    #pragma unroll
    for (int i = 0; i < 4; ++i)
        #pragma unroll
        for (int j = 0; j < 4; ++j)
            #pragma unroll
            for (int c = 0; c < 4; ++c) acc[i][j][c] = 0.f;

    const int KT = K / BKT;

    // prologue: load tile 0 into buffer 0
    {
        float4 a0 = *reinterpret_cast<const float4*>(&A[(long long)aRow * lda + aCol]);
        float4 a1 = *reinterpret_cast<const float4*>(&A[(long long)(aRow + 64) * lda + aCol]);
        As[0][aCol + 0][aRow] = f2tf32(a0.x);
        As[0][aCol + 1][aRow] = f2tf32(a0.y);
        As[0][aCol + 2][aRow] = f2tf32(a0.z);
        As[0][aCol + 3][aRow] = f2tf32(a0.w);
        As[0][aCol + 0][aRow + 64] = f2tf32(a1.x);
        As[0][aCol + 1][aRow + 64] = f2tf32(a1.y);
        As[0][aCol + 2][aRow + 64] = f2tf32(a1.z);
        As[0][aCol + 3][aRow + 64] = f2tf32(a1.w);
        float4 b0 = *reinterpret_cast<const float4*>(&B[(long long)bRow * ldb + bCol]);
        float4 b1 = *reinterpret_cast<const float4*>(&B[(long long)(bRow + 8) * ldb + bCol]);
        uint4 u0 = { f2tf32(b0.x), f2tf32(b0.y), f2tf32(b0.z), f2tf32(b0.w) };
        uint4 u1 = { f2tf32(b1.x), f2tf32(b1.y), f2tf32(b1.z), f2tf32(b1.w) };
        *reinterpret_cast<uint4*>(&Bs[0][bRow][bCol]) = u0;
        *reinterpret_cast<uint4*>(&Bs[0][bRow + 8][bCol]) = u1;
    }
    __syncthreads();

    for (int kt = 0; kt < KT; ++kt) {
        const int buf = kt & 1;
        float4 pa0, pa1, pb0, pb1;
        if (kt + 1 < KT) {
            const int k0 = (kt + 1) * BKT;
            pa0 = *reinterpret_cast<const float4*>(&A[(long long)aRow * lda + k0 + aCol]);
            pa1 = *reinterpret_cast<const float4*>(&A[(long long)(aRow + 64) * lda + k0 + aCol]);
            pb0 = *reinterpret_cast<const float4*>(&B[(long long)(k0 + bRow) * ldb + bCol]);
            pb1 = *reinterpret_cast<const float4*>(&B[(long long)(k0 + bRow + 8) * ldb + bCol]);
        }

        #pragma unroll
        for (int kk = 0; kk < BKT; kk += 8) {
            uint32_t af[4][4], bf[4][2];
            #pragma unroll
            for (int mt = 0; mt < 4; ++mt) {
                const int m = warpM + mt * 16;
                af[mt][0] = As[buf][kk + tg][m + g];
                af[mt][1] = As[buf][kk + tg][m + g + 8];
                af[mt][2] = As[buf][kk + tg + 4][m + g];
                af[mt][3] = As[buf][kk + tg + 4][m + g + 8];
            }
            #pragma unroll
            for (int nt = 0; nt < 4; ++nt) {
                const int n = warpN + nt * 8;
                bf[nt][0] = Bs[buf][kk + tg][n + g];
                bf[nt][1] = Bs[buf][kk + tg + 4][n + g];
            }
            #pragma unroll
            for (int mt = 0; mt < 4; ++mt)
                #pragma unroll
                for (int nt = 0; nt < 4; ++nt) {
                    asm volatile(
                        "mma.sync.aligned.m16n8k8.row.col.f32.tf32.tf32.f32 "
                        "{%0,%1,%2,%3}, {%4,%5,%6,%7}, {%8,%9}, {%0,%1,%2,%3};"
                        : "+f"(acc[mt][nt][0]), "+f"(acc[mt][nt][1]),
                          "+f"(acc[mt][nt][2]), "+f"(acc[mt][nt][3])
                        : "r"(af[mt][0]), "r"(af[mt][1]), "r"(af[mt][2]), "r"(af[mt][3]),
                          "r"(bf[nt][0]), "r"(bf[nt][1]));
                }
        }

        if (kt + 1 < KT) {
            const int nb = 1 - buf;
            As[nb][aCol + 0][aRow] = f2tf32(pa0.x);
            As[nb][aCol + 1][aRow] = f2tf32(pa0.y);
            As[nb][aCol + 2][aRow] = f2tf32(pa0.z);
            As[nb][aCol + 3][aRow] = f2tf32(pa0.w);
            As[nb][aCol + 0][aRow + 64] = f2tf32(pa1.x);
            As[nb][aCol + 1][aRow + 64] = f2tf32(pa1.y);
            As[nb][aCol + 2][aRow + 64] = f2tf32(pa1.z);
            As[nb][aCol + 3][aRow + 64] = f2tf32(pa1.w);
            uint4 u0 = { f2tf32(pb0.x), f2tf32(pb0.y), f2tf32(pb0.z), f2tf32(pb0.w) };
            uint4 u1 = { f2tf32(pb1.x), f2tf32(pb1.y), f2tf32(pb1.z), f2tf32(pb1.w) };
            *reinterpret_cast<uint4*>(&Bs[nb][bRow][bCol]) = u0;
            *reinterpret_cast<uint4*>(&Bs[nb][bRow + 8][bCol]) = u1;
            __syncthreads();
        }
    }

    // epilogue
    #pragma unroll
    for (int mt = 0; mt < 4; ++mt) {
        const int r0 = warpM + mt * 16 + g;
        #pragma unroll
        for (int nt = 0; nt < 4; ++nt) {
            const int c0 = warpN + nt * 8 + 2 * tg;
            float bx0 = 0.f, bx1 = 0.f;
            if (bias) {
                const int gcol = blockIdx.x * BN + c0;
                bx0 = bias[gcol];
                bx1 = bias[gcol + 1];
            }
            float2 lo = { alpha * acc[mt][nt][0] + bx0, alpha * acc[mt][nt][1] + bx1 };
            float2 hi = { alpha * acc[mt][nt][2] + bx0, alpha * acc[mt][nt][3] + bx1 };
            *reinterpret_cast<float2*>(&C[(long long)r0 * ldc + c0]) = lo;
            *reinterpret_cast<float2*>(&C[(long long)(r0 + 8) * ldc + c0]) = hi;
        }
    }
}

// ===========================================================================
// fp32 SIMT GEMM (kept for the tiny Wf step; full fp32 accuracy)
// ===========================================================================
__global__ __launch_bounds__(256) void sgemm_k(
    const float* __restrict__ A, int lda, long long sA,
    const float* __restrict__ B, int ldb, long long sB,
    float* __restrict__ C, int ldc, long long sC,
    int K, const float* __restrict__ bias, float alpha)
{
    __shared__ float As[8 * 128];
    __shared__ float Bs[8 * 128];
    const int tid = threadIdx.x;
    const int bx = blockIdx.x, by = blockIdx.y, bz = blockIdx.z;
    A += (long long)bz * sA + (long long)by * 128 * lda;
    B += (long long)bz * sB + (long long)bx * 128;
    C += (long long)bz * sC + (long long)by * 128 * ldc + (long long)bx * 128;
    const int aRow = tid >> 1, aCol = (tid & 1) << 2;
    const int bRow = tid >> 5, bCol = (tid & 31) << 2;
    const int tRow = (tid >> 4) * 8, tCol = (tid & 15) * 8;
    float acc[8][8] = {};
    float rM[8], rN[8];
    for (int k0 = 0; k0 < K; k0 += 8) {
        float4 a4 = *reinterpret_cast<const float4*>(&A[(long long)aRow * lda + k0 + aCol]);
        As[(aCol + 0) * 128 + aRow] = a4.x;
        As[(aCol + 1) * 128 + aRow] = a4.y;
        As[(aCol + 2) * 128 + aRow] = a4.z;
        As[(aCol + 3) * 128 + aRow] = a4.w;
        *reinterpret_cast<float4*>(&Bs[bRow * 128 + bCol]) =
            *reinterpret_cast<const float4*>(&B[(long long)(k0 + bRow) * ldb + bCol]);
        __syncthreads();
        #pragma unroll
        for (int kk = 0; kk < 8; ++kk) {
            #pragma unroll
            for (int i = 0; i < 8; ++i) rM[i] = As[kk * 128 + tRow + i];
            #pragma unroll
            for (int j = 0; j < 8; ++j) rN[j] = Bs[kk * 128 + tCol + j];
            #pragma unroll
            for (int i = 0; i < 8; ++i)
                #pragma unroll
                for (int j = 0; j < 8; ++j) acc[i][j] += rM[i] * rN[j];
        }
        __syncthreads();
    }
    #pragma unroll
    for (int i = 0; i < 8; ++i)
        #pragma unroll
        for (int j = 0; j < 8; j += 4) {
            float4 o;
            o.x = alpha * acc[i][j + 0]; o.y = alpha * acc[i][j + 1];
            o.z = alpha * acc[i][j + 2]; o.w = alpha * acc[i][j + 3];
            if (bias) {
                const int col = bx * 128 + tCol + j;
                o.x += bias[col]; o.y += bias[col + 1];
                o.z += bias[col + 2]; o.w += bias[col + 3];
            }
            *reinterpret_cast<float4*>(&C[(long long)(tRow + i) * ldc + tCol + j]) = o;
        }
}

// ===========================================================================
// Fused instance-norm(k,v) + partial dots
// ===========================================================================
__global__ __launch_bounds__(256) void norm_dots_partial(
    const float* __restrict__ kv, float* __restrict__ part)
{
    const int chunk = blockIdx.x;          // 0..NCHUNK-1
    const int bh    = blockIdx.y;          // 0..31
    const int b = bh >> 3, h = bh & 7;

    __shared__ float sk[64][65];
    __shared__ float sv[64][65];

    const int tid = threadIdx.x;
    const int e0 = (tid >> 4) << 2;
    const int f0 = (tid & 15) << 2;

    const float* base_k = kv + (long long)b * NTOK * (2 * INNER) + h * DH;
    const float* base_v = base_k + INNER;

    float acc[4][4] = {};

    for (int step = 0; step < CHUNKTOK / 64; ++step) {
        const int tok0 = chunk * CHUNKTOK + step * 64;
        for (int i = tid; i < 64 * 64; i += 256) {
            const int r = i >> 6, d = i & 63;
            const long long off = (long long)(tok0 + r) * (2 * INNER) + d;
            sk[r][d] = base_k[off];
            sv[r][d] = base_v[off];
        }
        __syncthreads();
        if (tid < 128) {
            const int r = tid & 63;
            float* row = (tid < 64) ? sk[r] : sv[r];
            float s = 0.f, s2 = 0.f;
            #pragma unroll 8
            for (int d = 0; d < 64; ++d) { float x = row[d]; s += x; s2 += x * x; }
            const float mu  = s * (1.0f / 64.0f);
            const float var = s2 * (1.0f / 64.0f) - mu * mu;
            const float inv = rsqrtf(var + 1e-5f);
            #pragma unroll 8
            for (int d = 0; d < 64; ++d) row[d] = (row[d] - mu) * inv;
        }
        __syncthreads();
        #pragma unroll 4
        for (int t = 0; t < 64; ++t) {
            float ke[4], vf[4];
            #pragma unroll
            for (int i = 0; i < 4; ++i) ke[i] = sk[t][e0 + i];
            #pragma unroll
            for (int j = 0; j < 4; ++j) vf[j] = sv[t][f0 + j];
            #pragma unroll
            for (int i = 0; i < 4; ++i)
                #pragma unroll
                for (int j = 0; j < 4; ++j) acc[i][j] += ke[i] * vf[j];
        }
        __syncthreads();
    }

    float* out = part + (long long)(bh * NCHUNK + chunk) * (DH * DH);
    #pragma unroll
    for (int i = 0; i < 4; ++i)
        #pragma unroll
        for (int j = 0; j < 4; ++j) out[(e0 + i) * DH + f0 + j] = acc[i][j];
}

__global__ __launch_bounds__(256) void reduce_dots(
    const float* __restrict__ part, float* __restrict__ dots)
{
    const int bh = blockIdx.x;
    for (int i = threadIdx.x; i < DH * DH; i += 256) {
        float s = 0.f;
        #pragma unroll
        for (int c = 0; c < NCHUNK; ++c)
            s += part[(long long)(bh * NCHUNK + c) * (DH * DH) + i];
        dots[bh * DH * DH + i] = s;
    }
}

// A2[b, h*64+e, j] = sum_f dots[b,h][e,f] * w_out[h*64+f, j]
// grid (32 bh, 4 jt): each block does 64 e x 64 j
__global__ __launch_bounds__(256) void dots_wout(
    const float* __restrict__ dots, const float* __restrict__ w_out,
    float* __restrict__ A2)
{
    const int bh = blockIdx.x;
    const int jt = blockIdx.y;
    const int b = bh >> 3, h = bh & 7;
    __shared__ float sd[DH * DH];
    __shared__ float sw[DH][65];
    for (int i = threadIdx.x; i < DH * DH; i += 256) {
        sd[i] = dots[bh * DH * DH + i];
        const int f = i >> 6, j = i & 63;
        sw[f][j] = w_out[(h * DH + f) * DIM + jt * 64 + j];
    }
    __syncthreads();
    for (int idx = threadIdx.x; idx < DH * 64; idx += 256) {
        const int e = idx >> 6;
        const int j = idx & 63;
        float s = 0.f;
        #pragma unroll 8
        for (int f = 0; f < DH; ++f) s += sd[e * DH + f] * sw[f][j];
        A2[((long long)b * INNER + h * DH + e) * DIM + jt * 64 + j] = s;
    }
}

// ---------------------------------------------------------------------------
extern "C" void kernel_launch(void* const* d_in, const int* in_sizes, int n_in,
                              void* d_out, int out_size)
{
    const float* x      = (const float*)d_in[0];  // [4, 8192, 256]
    const float* w_qkv  = (const float*)d_in[1];  // [256, 1536]
    const float* w_out  = (const float*)d_in[2];  // [512, 256]
    const float* b_out  = (const float*)d_in[3];  // [256]
    float*       out    = (float*)d_out;          // [4, 8192, 256]

    float *kv, *part, *dots, *A2, *Wf;
    cudaGetSymbolAddress((void**)&kv,   g_kv);
    cudaGetSymbolAddress((void**)&part, g_part);
    cudaGetSymbolAddress((void**)&dots, g_dots);
    cudaGetSymbolAddress((void**)&A2,   g_A2);
    cudaGetSymbolAddress((void**)&Wf,   g_Wf);

    // 1) kv = x @ w_qkv[:, 512:1536]   M=32768, N=1024, K=256  (tf32 TC)
    gemm_tf32<<<dim3((2 * INNER) / BN, (BATCH * NTOK) / BM, 1), 256>>>(
        x, DIM, 0,
        w_qkv + INNER, 3 * INNER, 0,
        kv, 2 * INNER, 0,
        DIM, nullptr, 1.0f);

    // 2) instance norm + partial dots + deterministic reduce
    norm_dots_partial<<<dim3(NCHUNK, 32), 256>>>(kv, part);
    reduce_dots<<<32, 256>>>(part, dots);

    // 3) A2 = blockdiag(dots) @ w_out ; Wf[b] = w_q @ A2[b] / n  (fp32)
    dots_wout<<<dim3(32, 4), 256>>>(dots, w_out, A2);
    sgemm_k<<<dim3(DIM / 128, DIM / 128, BATCH), 256>>>(
        w_qkv, 3 * INNER, 0,
        A2, DIM, (long long)INNER * DIM,
        Wf, DIM, (long long)DIM * DIM,
        INNER, nullptr, 1.0f / (float)NTOK);

    // 4) out[b] = x[b] @ Wf[b] + b_out   M=8192, N=256, K=256 per batch (tf32 TC)
    gemm_tf32<<<dim3(DIM / BN, NTOK / BM, BATCH), 256>>>(
        x, DIM, (long long)NTOK * DIM,
        Wf, DIM, (long long)DIM * DIM,
        out, DIM, (long long)NTOK * DIM,
        DIM, b_out, 1.0f);
}

// round 3
// speedup vs baseline: 3.5116x; 1.1908x over previous
#include <cuda_runtime.h>
#include <cuda_bf16.h>
#include <cstdint>

// ---------------------------------------------------------------------------
// Galerkin linear attention, restructured:
//   [fused] k,v = x @ w_{k,v};  instance-norm rows;  part = k-hat^T v-hat
//   dots = sum_chunks part ; A2 = blockdiag(dots)@w_out ; Wf[b]=w_q@A2[b]/n
//   out[b] = x[b] @ Wf[b] + b_out     (tf32 tensor-core GEMM)
// ---------------------------------------------------------------------------

#define BATCH   4
#define NTOK    8192
#define DIM     256
#define HEADS   8
#define DH      64
#define INNER   512
#define TCH     128                 // tokens per fused chunk
#define NCH     (NTOK / TCH)        // 64

__device__ float g_part[32 * NCH * DH * DH];   // 33.5 MB partial dots
__device__ float g_dots[32 * DH * DH];
__device__ float g_A2[BATCH * INNER * DIM];
__device__ float g_Wf[BATCH * DIM * DIM];

__device__ __forceinline__ uint32_t f2tf32(float f) {
    uint32_t r;
    asm("cvt.rna.tf32.f32 %0, %1;" : "=r"(r) : "f"(f));
    return r;
}

__device__ __forceinline__ void mma_tf32(float* d, const uint32_t* a, const uint32_t* b) {
    asm volatile(
        "mma.sync.aligned.m16n8k8.row.col.f32.tf32.tf32.f32 "
        "{%0,%1,%2,%3}, {%4,%5,%6,%7}, {%8,%9}, {%0,%1,%2,%3};"
        : "+f"(d[0]), "+f"(d[1]), "+f"(d[2]), "+f"(d[3])
        : "r"(a[0]), "r"(a[1]), "r"(a[2]), "r"(a[3]), "r"(b[0]), "r"(b[1]));
}

// ===========================================================================
// Fused: k/v projection (tf32 mma) + in-register instance norm + split-tf32
// partial dots. grid(NCH, 32), 256 threads, dynamic smem.
// ===========================================================================
#define PA 136     // As pitch (8*tg+g conflict-free)
#define PB 72      // Bk/Bv pitch
#define PS 72      // sk/sv pitch
#define FUSED_SMEM ((2*16*PA + 2*2*16*PB) * 4 + 2 * TCH * PS * 4)

__global__ __launch_bounds__(256) void fused_kv_dots(
    const float* __restrict__ x, const float* __restrict__ w_qkv,
    float* __restrict__ part)
{
    extern __shared__ unsigned char smraw[];
    uint32_t* As = (uint32_t*)smraw;           // [2][16][PA]  (x tile, tf32, [k][m])
    uint32_t* Bk = As + 2 * 16 * PA;           // [2][16][PB]
    uint32_t* Bv = Bk + 2 * 16 * PB;
    float* sk = (float*)(Bv + 2 * 16 * PB);    // [TCH][PS] normalized k-hat
    float* sv = sk + TCH * PS;                 // [TCH][PS] normalized v-hat

    const int tid = threadIdx.x;
    const int chunk = blockIdx.x, bh = blockIdx.y;
    const int b = bh >> 3, h = bh & 7;

    const float* xA  = x + ((long long)b * NTOK + (long long)chunk * TCH) * DIM;
    const float* wkp = w_qkv + INNER + h * DH;        // stride 3*INNER
    const float* wvp = w_qkv + 2 * INNER + h * DH;

    const int xRow = tid >> 1, xC = (tid & 1) * 8;    // x: 128 rows x 16 cols
    const int wR = tid >> 4, wC = (tid & 15) * 4;     // w: 16 rows x 64 cols

    const int lane = tid & 31, wid = tid >> 5;
    const int g = lane >> 2, tg = lane & 3;
    const bool isV = (wid >= 4);
    const int warpM = (isV ? wid - 4 : wid) * 32;

    float acc[2][8][4];
    #pragma unroll
    for (int i = 0; i < 2; ++i)
        #pragma unroll
        for (int j = 0; j < 8; ++j)
            #pragma unroll
            for (int c = 0; c < 4; ++c) acc[i][j][c] = 0.f;

    // ---- phase 1: k/v = x @ w (K=256, 16 tiles of 16, double-buffered) ----
    float4 pa0, pa1, pk4, pv4;
    {
        pa0 = *(const float4*)&xA[(long long)xRow * DIM + xC];
        pa1 = *(const float4*)&xA[(long long)xRow * DIM + xC + 4];
        pk4 = *(const float4*)&wkp[(long long)wR * (3 * INNER) + wC];
        pv4 = *(const float4*)&wvp[(long long)wR * (3 * INNER) + wC];
    }
    // store tile 0
    {
        As[(0 * 16 + xC + 0) * 1 + 0] = 0; // (dummy to keep compiler honest removed below)
    }
    // real store of tile 0
    As[(xC + 0) * PA + xRow] = f2tf32(pa0.x);
    As[(xC + 1) * PA + xRow] = f2tf32(pa0.y);
    As[(xC + 2) * PA + xRow] = f2tf32(pa0.z);
    As[(xC + 3) * PA + xRow] = f2tf32(pa0.w);
    As[(xC + 4) * PA + xRow] = f2tf32(pa1.x);
    As[(xC + 5) * PA + xRow] = f2tf32(pa1.y);
    As[(xC + 6) * PA + xRow] = f2tf32(pa1.z);
    As[(xC + 7) * PA + xRow] = f2tf32(pa1.w);
    Bk[wR * PB + wC + 0] = f2tf32(pk4.x);
    Bk[wR * PB + wC + 1] = f2tf32(pk4.y);
    Bk[wR * PB + wC + 2] = f2tf32(pk4.z);
    Bk[wR * PB + wC + 3] = f2tf32(pk4.w);
    Bv[wR * PB + wC + 0] = f2tf32(pv4.x);
    Bv[wR * PB + wC + 1] = f2tf32(pv4.y);
    Bv[wR * PB + wC + 2] = f2tf32(pv4.z);
    Bv[wR * PB + wC + 3] = f2tf32(pv4.w);
    __syncthreads();

    const uint32_t* Bsel = isV ? Bv : Bk;

    for (int kt = 0; kt < 16; ++kt) {
        const int buf = kt & 1;
        if (kt + 1 < 16) {
            const int k0 = (kt + 1) * 16;
            pa0 = *(const float4*)&xA[(long long)xRow * DIM + k0 + xC];
            pa1 = *(const float4*)&xA[(long long)xRow * DIM + k0 + xC + 4];
            pk4 = *(const float4*)&wkp[(long long)(k0 + wR) * (3 * INNER) + wC];
            pv4 = *(const float4*)&wvp[(long long)(k0 + wR) * (3 * INNER) + wC];
        }

        #pragma unroll
        for (int kk = 0; kk < 16; kk += 8) {
            uint32_t af[2][4], bf[8][2];
            #pragma unroll
            for (int mt = 0; mt < 2; ++mt) {
                const int m = warpM + mt * 16;
                af[mt][0] = As[(buf * 16 + kk + tg) * PA + m + g];
                af[mt][1] = As[(buf * 16 + kk + tg) * PA + m + g + 8];
                af[mt][2] = As[(buf * 16 + kk + tg + 4) * PA + m + g];
                af[mt][3] = As[(buf * 16 + kk + tg + 4) * PA + m + g + 8];
            }
            #pragma unroll
            for (int nt = 0; nt < 8; ++nt) {
                bf[nt][0] = Bsel[(buf * 16 + kk + tg) * PB + nt * 8 + g];
                bf[nt][1] = Bsel[(buf * 16 + kk + tg + 4) * PB + nt * 8 + g];
            }
            #pragma unroll
            for (int mt = 0; mt < 2; ++mt)
                #pragma unroll
                for (int nt = 0; nt < 8; ++nt)
                    mma_tf32(acc[mt][nt], af[mt], bf[nt]);
        }

        if (kt + 1 < 16) {
            const int nb = 1 - buf;
            As[(nb * 16 + xC + 0) * PA + xRow] = f2tf32(pa0.x);
            As[(nb * 16 + xC + 1) * PA + xRow] = f2tf32(pa0.y);
            As[(nb * 16 + xC + 2) * PA + xRow] = f2tf32(pa0.z);
            As[(nb * 16 + xC + 3) * PA + xRow] = f2tf32(pa0.w);
            As[(nb * 16 + xC + 4) * PA + xRow] = f2tf32(pa1.x);
            As[(nb * 16 + xC + 5) * PA + xRow] = f2tf32(pa1.y);
            As[(nb * 16 + xC + 6) * PA + xRow] = f2tf32(pa1.z);
            As[(nb * 16 + xC + 7) * PA + xRow] = f2tf32(pa1.w);
            Bk[(nb * 16 + wR) * PB + wC + 0] = f2tf32(pk4.x);
            Bk[(nb * 16 + wR) * PB + wC + 1] = f2tf32(pk4.y);
            Bk[(nb * 16 + wR) * PB + wC + 2] = f2tf32(pk4.z);
            Bk[(nb * 16 + wR) * PB + wC + 3] = f2tf32(pk4.w);
            Bv[(nb * 16 + wR) * PB + wC + 0] = f2tf32(pv4.x);
            Bv[(nb * 16 + wR) * PB + wC + 1] = f2tf32(pv4.y);
            Bv[(nb * 16 + wR) * PB + wC + 2] = f2tf32(pv4.z);
            Bv[(nb * 16 + wR) * PB + wC + 3] = f2tf32(pv4.w);
            __syncthreads();
        }
    }

    // ---- phase 2: in-register instance norm (rows spread over 4 lanes tg) ----
    float* sdst = isV ? sv : sk;
    #pragma unroll
    for (int mt = 0; mt < 2; ++mt) {
        #pragma unroll
        for (int rr = 0; rr < 2; ++rr) {       // rr=0 -> regs {0,1}; rr=1 -> {2,3}
            float s = 0.f, q = 0.f;
            #pragma unroll
            for (int nt = 0; nt < 8; ++nt) {
                float v0 = acc[mt][nt][2 * rr], v1 = acc[mt][nt][2 * rr + 1];
                s += v0 + v1;
                q += v0 * v0 + v1 * v1;
            }
            s += __shfl_xor_sync(0xFFFFFFFFu, s, 1);
            s += __shfl_xor_sync(0xFFFFFFFFu, s, 2);
            q += __shfl_xor_sync(0xFFFFFFFFu, q, 1);
            q += __shfl_xor_sync(0xFFFFFFFFu, q, 2);
            const float mu  = s * (1.0f / 64.0f);
            const float var = q * (1.0f / 64.0f) - mu * mu;
            const float inv = rsqrtf(var + 1e-5f);
            const int row = warpM + mt * 16 + g + rr * 8;
            #pragma unroll
            for (int nt = 0; nt < 8; ++nt) {
                float2 o = { (acc[mt][nt][2 * rr] - mu) * inv,
                             (acc[mt][nt][2 * rr + 1] - mu) * inv };
                *(float2*)&sdst[row * PS + nt * 8 + 2 * tg] = o;
            }
        }
    }
    __syncthreads();

    // ---- phase 3: partial dots = k-hat^T @ v-hat  (split tf32: hh+hl+lh) ----
    const int n0 = wid * 8;
    float d[4][4];
    #pragma unroll
    for (int mt = 0; mt < 4; ++mt)
        #pragma unroll
        for (int c = 0; c < 4; ++c) d[mt][c] = 0.f;

    for (int kk = 0; kk < TCH; kk += 8) {
        uint32_t ah[4][4], al[4][4], bhv[2], blv[2];
        #pragma unroll
        for (int mt = 0; mt < 4; ++mt) {
            const int m = mt * 16;
            float f0 = sk[(kk + tg) * PS + m + g];
            float f1 = sk[(kk + tg) * PS + m + g + 8];
            float f2 = sk[(kk + tg + 4) * PS + m + g];
            float f3 = sk[(kk + tg + 4) * PS + m + g + 8];
            ah[mt][0] = f2tf32(f0); al[mt][0] = f2tf32(f0 - __uint_as_float(ah[mt][0]));
            ah[mt][1] = f2tf32(f1); al[mt][1] = f2tf32(f1 - __uint_as_float(ah[mt][1]));
            ah[mt][2] = f2tf32(f2); al[mt][2] = f2tf32(f2 - __uint_as_float(ah[mt][2]));
            ah[mt][3] = f2tf32(f3); al[mt][3] = f2tf32(f3 - __uint_as_float(ah[mt][3]));
        }
        {
            float e0 = sv[(kk + tg) * PS + n0 + g];
            float e1 = sv[(kk + tg + 4) * PS + n0 + g];
            bhv[0] = f2tf32(e0); blv[0] = f2tf32(e0 - __uint_as_float(bhv[0]));
            bhv[1] = f2tf32(e1); blv[1] = f2tf32(e1 - __uint_as_float(bhv[1]));
        }
        #pragma unroll
        for (int mt = 0; mt < 4; ++mt) mma_tf32(d[mt], ah[mt], bhv);
        #pragma unroll
        for (int mt = 0; mt < 4; ++mt) mma_tf32(d[mt], ah[mt], blv);
        #pragma unroll
        for (int mt = 0; mt < 4; ++mt) mma_tf32(d[mt], al[mt], bhv);
    }

    float* op = part + (long long)(bh * NCH + chunk) * (DH * DH);
    #pragma unroll
    for (int mt = 0; mt < 4; ++mt) {
        const int e = mt * 16 + g;
        float2 lo = { d[mt][0], d[mt][1] };
        float2 hi = { d[mt][2], d[mt][3] };
        *(float2*)&op[e * DH + n0 + 2 * tg] = lo;
        *(float2*)&op[(e + 8) * DH + n0 + 2 * tg] = hi;
    }
}

// ===========================================================================
__global__ __launch_bounds__(256) void reduce_dots(
    const float* __restrict__ part, float* __restrict__ dots)
{
    const int bh = blockIdx.x, seg = blockIdx.y;   // grid (32,4)
    #pragma unroll
    for (int j = 0; j < 4; ++j) {
        const int idx = seg * 1024 + j * 256 + threadIdx.x;
        float s = 0.f;
        #pragma unroll 8
        for (int c = 0; c < NCH; ++c)
            s += part[(long long)(bh * NCH + c) * (DH * DH) + idx];
        dots[bh * DH * DH + idx] = s;
    }
}

// A2[b, h*64+e, j] = sum_f dots[b,h][e,f] * w_out[h*64+f, j]; grid (32, 8)
__global__ __launch_bounds__(256) void dots_wout(
    const float* __restrict__ dots, const float* __restrict__ w_out,
    float* __restrict__ A2)
{
    const int bh = blockIdx.x, jt = blockIdx.y;
    const int b = bh >> 3, h = bh & 7;
    __shared__ float sd[DH * DH];
    __shared__ float sw[DH][33];
    for (int i = threadIdx.x; i < DH * DH; i += 256) sd[i] = dots[bh * DH * DH + i];
    for (int i = threadIdx.x; i < DH * 32; i += 256) {
        const int f = i >> 5, j = i & 31;
        sw[f][j] = w_out[(h * DH + f) * DIM + jt * 32 + j];
    }
    __syncthreads();
    for (int idx = threadIdx.x; idx < DH * 32; idx += 256) {
        const int e = idx >> 5, j = idx & 31;
        float s = 0.f;
        #pragma unroll 8
        for (int f = 0; f < DH; ++f) s += sd[e * DH + f] * sw[f][j];
        A2[((long long)b * INNER + h * DH + e) * DIM + jt * 32 + j] = s;
    }
}

// ===========================================================================
// fp32 SIMT GEMM (tiny Wf step)
// ===========================================================================
__global__ __launch_bounds__(256) void sgemm_k(
    const float* __restrict__ A, int lda, long long sA,
    const float* __restrict__ B, int ldb, long long sB,
    float* __restrict__ C, int ldc, long long sC,
    int K, const float* __restrict__ bias, float alpha)
{
    __shared__ float As[8 * 128];
    __shared__ float Bs[8 * 128];
    const int tid = threadIdx.x;
    const int bx = blockIdx.x, by = blockIdx.y, bz = blockIdx.z;
    A += (long long)bz * sA + (long long)by * 128 * lda;
    B += (long long)bz * sB + (long long)bx * 128;
    C += (long long)bz * sC + (long long)by * 128 * ldc + (long long)bx * 128;
    const int aRow = tid >> 1, aCol = (tid & 1) << 2;
    const int bRow = tid >> 5, bCol = (tid & 31) << 2;
    const int tRow = (tid >> 4) * 8, tCol = (tid & 15) * 8;
    float acc[8][8] = {};
    float rM[8], rN[8];
    for (int k0 = 0; k0 < K; k0 += 8) {
        float4 a4 = *reinterpret_cast<const float4*>(&A[(long long)aRow * lda + k0 + aCol]);
        As[(aCol + 0) * 128 + aRow] = a4.x;
        As[(aCol + 1) * 128 + aRow] = a4.y;
        As[(aCol + 2) * 128 + aRow] = a4.z;
        As[(aCol + 3) * 128 + aRow] = a4.w;
        *reinterpret_cast<float4*>(&Bs[bRow * 128 + bCol]) =
            *reinterpret_cast<const float4*>(&B[(long long)(k0 + bRow) * ldb + bCol]);
        __syncthreads();
        #pragma unroll
        for (int kk = 0; kk < 8; ++kk) {
            #pragma unroll
            for (int i = 0; i < 8; ++i) rM[i] = As[kk * 128 + tRow + i];
            #pragma unroll
            for (int j = 0; j < 8; ++j) rN[j] = Bs[kk * 128 + tCol + j];
            #pragma unroll
            for (int i = 0; i < 8; ++i)
                #pragma unroll
                for (int j = 0; j < 8; ++j) acc[i][j] += rM[i] * rN[j];
        }
        __syncthreads();
    }
    #pragma unroll
    for (int i = 0; i < 8; ++i)
        #pragma unroll
        for (int j = 0; j < 8; j += 4) {
            float4 o;
            o.x = alpha * acc[i][j + 0]; o.y = alpha * acc[i][j + 1];
            o.z = alpha * acc[i][j + 2]; o.w = alpha * acc[i][j + 3];
            if (bias) {
                const int col = bx * 128 + tCol + j;
                o.x += bias[col]; o.y += bias[col + 1];
                o.z += bias[col + 2]; o.w += bias[col + 3];
            }
            *reinterpret_cast<float4*>(&C[(long long)(tRow + i) * ldc + tCol + j]) = o;
        }
}

// ===========================================================================
// TF32 tensor-core GEMM for the final out = x @ Wf + b_out
// ===========================================================================
__global__ __launch_bounds__(256) void gemm_tf32(
    const float* __restrict__ A, int lda, long long sA,
    const float* __restrict__ B, int ldb, long long sB,
    float* __restrict__ C, int ldc, long long sC,
    int K, const float* __restrict__ bias, float alpha)
{
    __shared__ uint32_t As[2][16][132];
    __shared__ uint32_t Bs[2][16][132];

    const int tid = threadIdx.x;
    const int bx = blockIdx.x, by = blockIdx.y, bz = blockIdx.z;

    A += (long long)bz * sA + (long long)by * 128 * lda;
    B += (long long)bz * sB + (long long)bx * 128;
    C += (long long)bz * sC + (long long)by * 128 * ldc + (long long)bx * 128;

    const int aRow = tid >> 2, aCol = (tid & 3) << 2;
    const int bRow = tid >> 5, bCol = (tid & 31) << 2;

    const int lane = tid & 31, wid = tid >> 5;
    const int warpM = (wid >> 2) * 64;
    const int warpN = (wid & 3) * 32;
    const int g = lane >> 2, tg = lane & 3;

    float acc[4][4][4];
    #pragma unroll
    for (int i = 0; i < 4; ++i)
        #pragma unroll
        for (int j = 0; j < 4; ++j)
            #pragma unroll
            for (int c = 0; c < 4; ++c) acc[i][j][c] = 0.f;

    const int KT = K / 16;

    {
        float4 a0 = *reinterpret_cast<const float4*>(&A[(long long)aRow * lda + aCol]);
        float4 a1 = *reinterpret_cast<const float4*>(&A[(long long)(aRow + 64) * lda + aCol]);
        As[0][aCol + 0][aRow] = f2tf32(a0.x);
        As[0][aCol + 1][aRow] = f2tf32(a0.y);
        As[0][aCol + 2][aRow] = f2tf32(a0.z);
        As[0][aCol + 3][aRow] = f2tf32(a0.w);
        As[0][aCol + 0][aRow + 64] = f2tf32(a1.x);
        As[0][aCol + 1][aRow + 64] = f2tf32(a1.y);
        As[0][aCol + 2][aRow + 64] = f2tf32(a1.z);
        As[0][aCol + 3][aRow + 64] = f2tf32(a1.w);
        float4 b0 = *reinterpret_cast<const float4*>(&B[(long long)bRow * ldb + bCol]);
        float4 b1 = *reinterpret_cast<const float4*>(&B[(long long)(bRow + 8) * ldb + bCol]);
        Bs[0][bRow][bCol + 0] = f2tf32(b0.x);
        Bs[0][bRow][bCol + 1] = f2tf32(b0.y);
        Bs[0][bRow][bCol + 2] = f2tf32(b0.z);
        Bs[0][bRow][bCol + 3] = f2tf32(b0.w);
        Bs[0][bRow + 8][bCol + 0] = f2tf32(b1.x);
        Bs[0][bRow + 8][bCol + 1] = f2tf32(b1.y);
        Bs[0][bRow + 8][bCol + 2] = f2tf32(b1.z);
        Bs[0][bRow + 8][bCol + 3] = f2tf32(b1.w);
    }
    __syncthreads();

    for (int kt = 0; kt < KT; ++kt) {
        const int buf = kt & 1;
        float4 pa0, pa1, pb0, pb1;
        if (kt + 1 < KT) {
            const int k0 = (kt + 1) * 16;
            pa0 = *reinterpret_cast<const float4*>(&A[(long long)aRow * lda + k0 + aCol]);
            pa1 = *reinterpret_cast<const float4*>(&A[(long long)(aRow + 64) * lda + k0 + aCol]);
            pb0 = *reinterpret_cast<const float4*>(&B[(long long)(k0 + bRow) * ldb + bCol]);
            pb1 = *reinterpret_cast<const float4*>(&B[(long long)(k0 + bRow + 8) * ldb + bCol]);
        }

        #pragma unroll
        for (int kk = 0; kk < 16; kk += 8) {
            uint32_t af[4][4], bf[4][2];
            #pragma unroll
            for (int mt = 0; mt < 4; ++mt) {
                const int m = warpM + mt * 16;
                af[mt][0] = As[buf][kk + tg][m + g];
                af[mt][1] = As[buf][kk + tg][m + g + 8];
                af[mt][2] = As[buf][kk + tg + 4][m + g];
                af[mt][3] = As[buf][kk + tg + 4][m + g + 8];
            }
            #pragma unroll
            for (int nt = 0; nt < 4; ++nt) {
                const int n = warpN + nt * 8;
                bf[nt][0] = Bs[buf][kk + tg][n + g];
                bf[nt][1] = Bs[buf][kk + tg + 4][n + g];
            }
            #pragma unroll
            for (int mt = 0; mt < 4; ++mt)
                #pragma unroll
                for (int nt = 0; nt < 4; ++nt)
                    mma_tf32(acc[mt][nt], af[mt], bf[nt]);
        }

        if (kt + 1 < KT) {
            const int nb = 1 - buf;
            As[nb][aCol + 0][aRow] = f2tf32(pa0.x);
            As[nb][aCol + 1][aRow] = f2tf32(pa0.y);
            As[nb][aCol + 2][aRow] = f2tf32(pa0.z);
            As[nb][aCol + 3][aRow] = f2tf32(pa0.w);
            As[nb][aCol + 0][aRow + 64] = f2tf32(pa1.x);
            As[nb][aCol + 1][aRow + 64] = f2tf32(pa1.y);
            As[nb][aCol + 2][aRow + 64] = f2tf32(pa1.z);
            As[nb][aCol + 3][aRow + 64] = f2tf32(pa1.w);
            Bs[nb][bRow][bCol + 0] = f2tf32(pb0.x);
            Bs[nb][bRow][bCol + 1] = f2tf32(pb0.y);
            Bs[nb][bRow][bCol + 2] = f2tf32(pb0.z);
            Bs[nb][bRow][bCol + 3] = f2tf32(pb0.w);
            Bs[nb][bRow + 8][bCol + 0] = f2tf32(pb1.x);
            Bs[nb][bRow + 8][bCol + 1] = f2tf32(pb1.y);
            Bs[nb][bRow + 8][bCol + 2] = f2tf32(pb1.z);
            Bs[nb][bRow + 8][bCol + 3] = f2tf32(pb1.w);
            __syncthreads();
        }
    }

    #pragma unroll
    for (int mt = 0; mt < 4; ++mt) {
        const int r0 = warpM + mt * 16 + g;
        #pragma unroll
        for (int nt = 0; nt < 4; ++nt) {
            const int c0 = warpN + nt * 8 + 2 * tg;
            float bx0 = 0.f, bx1 = 0.f;
            if (bias) {
                const int gcol = blockIdx.x * 128 + c0;
                bx0 = bias[gcol];
                bx1 = bias[gcol + 1];
            }
            float2 lo = { alpha * acc[mt][nt][0] + bx0, alpha * acc[mt][nt][1] + bx1 };
            float2 hi = { alpha * acc[mt][nt][2] + bx0, alpha * acc[mt][nt][3] + bx1 };
            *reinterpret_cast<float2*>(&C[(long long)r0 * ldc + c0]) = lo;
            *reinterpret_cast<float2*>(&C[(long long)(r0 + 8) * ldc + c0]) = hi;
        }
    }
}

// ---------------------------------------------------------------------------
extern "C" void kernel_launch(void* const* d_in, const int* in_sizes, int n_in,
                              void* d_out, int out_size)
{
    const float* x      = (const float*)d_in[0];  // [4, 8192, 256]
    const float* w_qkv  = (const float*)d_in[1];  // [256, 1536]
    const float* w_out  = (const float*)d_in[2];  // [512, 256]
    const float* b_out  = (const float*)d_in[3];  // [256]
    float*       out    = (float*)d_out;          // [4, 8192, 256]

    float *part, *dots, *A2, *Wf;
    cudaGetSymbolAddress((void**)&part, g_part);
    cudaGetSymbolAddress((void**)&dots, g_dots);
    cudaGetSymbolAddress((void**)&A2,   g_A2);
    cudaGetSymbolAddress((void**)&Wf,   g_Wf);

    cudaFuncSetAttribute(fused_kv_dots,
                         cudaFuncAttributeMaxDynamicSharedMemorySize, FUSED_SMEM);

    // 1) fused: k/v projection + instance norm + partial dots
    fused_kv_dots<<<dim3(NCH, 32), 256, FUSED_SMEM>>>(x, w_qkv, part);

    // 2) deterministic chunk reduction
    reduce_dots<<<dim3(32, 4), 256>>>(part, dots);

    // 3) A2 = blockdiag(dots) @ w_out ; Wf[b] = w_q @ A2[b] / n
    dots_wout<<<dim3(32, 8), 256>>>(dots, w_out, A2);
    sgemm_k<<<dim3(DIM / 128, DIM / 128, BATCH), 256>>>(
        w_qkv, 3 * INNER, 0,
        A2, DIM, (long long)INNER * DIM,
        Wf, DIM, (long long)DIM * DIM,
        INNER, nullptr, 1.0f / (float)NTOK);

    // 4) out[b] = x[b] @ Wf[b] + b_out  (tf32 TC)
    gemm_tf32<<<dim3(DIM / 128, NTOK / 128, BATCH), 256>>>(
        x, DIM, (long long)NTOK * DIM,
        Wf, DIM, (long long)DIM * DIM,
        out, DIM, (long long)NTOK * DIM,
        DIM, b_out, 1.0f);
}